// round 12
// baseline (speedup 1.0000x reference)
#include <cuda_runtime.h>
#include <cstdint>
#include <cstddef>

// Problem constants
#define Bm   64     // batch (GEMM M)
#define Sk   720    // seq len (GEMM K)
#define Cc   321    // channels
#define Pp   336    // pred len (GEMM N)
#define WIN  25
#define HALO 12

// Tiling
#define NT   112    // N per block (336 = 3*112)
#define KT   48     // K tile (720 = 15*48)
#define KEXT 72     // KT + 2*HALO
#define NCHUNK 18   // KEXT/4 float4 chunks per W row
#define THREADS 224 // 16 (tm) x 14 (tn)

// smem leading dims (floats).
// SA_LD 64: A reads are row-internal (same k across warp) -> stride-free.
// SW_LD 76: 304B row stride == 48 (mod 128) -> strided LDS.128 is
//           wavefront-optimal (8 lanes per 128B line).
// SB_LD 112: permuted column layout (see w(n) below).
#define SA_LD 64
#define SW_LD 76
#define SB_LD 112

#define SMEM_FLOATS (KT*SA_LD + 2*NT*SW_LD + (KT+1)*SB_LD + 8)
#define SMEM_BYTES  (SMEM_FLOATS * 4)   // 102,368 B -> 2 CTAs/SM

// Scratch: x rearranged to [c][s][b] (59.2 MB)
__device__ float g_xT[(size_t)Cc * Sk * Bm];

__device__ __forceinline__ unsigned smem_u32(const void* p) {
    return (unsigned)__cvta_generic_to_shared(p);
}
__device__ __forceinline__ void cp16(unsigned dst, const void* src, unsigned sz) {
    asm volatile("cp.async.ca.shared.global [%0], [%1], 16, %2;"
                 :: "r"(dst), "l"(src), "r"(sz));
}

// ---------------------------------------------------------------------------
// Kernel 1: x [b][s][c] -> g_xT [c][s][b]
// ---------------------------------------------------------------------------
__global__ void transpose_kernel(const float* __restrict__ x) {
    __shared__ float tile[32][33];
    int s  = blockIdx.y;
    int c0 = blockIdx.x * 32;
    int b0 = blockIdx.z * 32;
    int tx = threadIdx.x, ty = threadIdx.y;

    #pragma unroll
    for (int i = 0; i < 4; i++) {
        int b = b0 + ty + 8*i, c = c0 + tx;
        if (c < Cc)
            tile[ty + 8*i][tx] = x[((size_t)b * Sk + s) * Cc + c];
    }
    __syncthreads();
    #pragma unroll
    for (int i = 0; i < 4; i++) {
        int c = c0 + ty + 8*i, b = b0 + tx;
        if (c < Cc)
            g_xT[((size_t)c * Sk + s) * Bm + b] = tile[tx][ty + 8*i];
    }
}

// ---------------------------------------------------------------------------
// Kernel 2: folded GEMM.
//   out[b,c,p] = sum_s xT[c][s][b] * W_eff[c][p][s] + b_res + b_trend
//   W_eff[p,s] = W_res[p,s] + (1/25)*sum_{t in [s-12,s+12] ∩ [0,Sk)} (W_trd-W_res)[p,t]
// sBe stores column n at PERMUTED word w(n) so each thread's 4 n-pairs
// (p = 2tn + 28j + v) occupy two 16B-contiguous groups:
//   w = 56*(j/2) + 4*tn + 2*(j%2) + v
// FMA loop: per k, 1x LDS.128 (A) + 2x LDS.128 (B) + 4 dup movs + 16 FMA2.
// ---------------------------------------------------------------------------
__global__ __launch_bounds__(THREADS, 2) void dlinear_gemm(
    const float* __restrict__ Wres, const float* __restrict__ bres,
    const float* __restrict__ Wtrd, const float* __restrict__ btrd,
    float* __restrict__ out)
{
    extern __shared__ float smem[];
    float* sA  = smem;                      // [KT][SA_LD]    x tile, [k][m]
    float* sWr = sA  + KT * SA_LD;          // [NT][SW_LD]    W_res extended (raw)
    float* sWt = sWr + NT * SW_LD;          // [NT][SW_LD]    W_trd extended (raw)
    float* sBe = sWt + NT * SW_LD;          // [KT+1][SB_LD]  W_eff tile, permuted cols

    const int c   = blockIdx.y;
    const int n0  = blockIdx.x * NT;
    const int tid = threadIdx.x;
    const int tm  = tid / 14;   // 0..15 -> m base = 4*tm
    const int tn  = tid % 14;   // 0..13 -> n pairs at 2*tn + 28*j

    const float* xT = g_xT + (size_t)c * Sk * Bm;
    const float* wr = Wres + ((size_t)c * Pp + n0) * Sk;
    const float* wt = Wtrd + ((size_t)c * Pp + n0) * Sk;

    unsigned long long acc[4][4];
    #pragma unroll
    for (int i = 0; i < 4; i++)
        #pragma unroll
        for (int j = 0; j < 4; j++) acc[i][j] = 0ULL;

    const float* pA = sA + tm * 4;
    const char*  pB = (const char*)(sBe + tn * 4);   // 16B group base

    for (int k0 = 0; k0 < Sk; k0 += KT) {
        // ---- A tile via cp.async: KT rows x 16 chunks = 768 ----
        #pragma unroll
        for (int j = 0; j < 4; j++) {
            int idx = tid + THREADS * j;
            if (idx < KT * 16) {
                int k = idx >> 4, ci = idx & 15;
                cp16(smem_u32(sA + k * SA_LD + ci * 4),
                     xT + (size_t)(k0 + k) * Bm + ci * 4, 16u);
            }
        }
        // ---- W ext tiles via cp.async: 2 * NT * NCHUNK = 4032 = 224*18 ----
        #pragma unroll
        for (int j = 0; j < 2 * NCHUNK; j++) {
            int idx = tid + THREADS * j;
            int t   = idx / (NT * NCHUNK);           // 0 = Wres, 1 = Wtrd
            int rem = idx - t * (NT * NCHUNK);
            int n   = rem / NCHUNK, ci = rem % NCHUNK;
            int s0  = k0 - HALO + ci * 4;
            unsigned ok = (s0 >= 0 && s0 <= Sk - 4) ? 16u : 0u;
            int s0c = s0 < 0 ? 0 : (s0 > Sk - 4 ? Sk - 4 : s0);
            const float* src = (t ? wt : wr) + (size_t)n * Sk + s0c;
            float* dst = (t ? sWt : sWr) + n * SW_LD + ci * 4;
            cp16(smem_u32(dst), src, ok);
        }
        asm volatile("cp.async.commit_group;" ::: "memory");
        asm volatile("cp.async.wait_group 0;" ::: "memory");
        __syncthreads();

        // ---- build W_eff: 224 threads = 112 n x 2 chunk-halves of 6 groups ----
        {
            int n  = tid % NT;
            int cb = (tid / NT) * 6;          // chunk base (kb = 4*cb)
            const float4* wr4 = (const float4*)(sWr + n * SW_LD);
            const float4* wt4 = (const float4*)(sWt + n * SW_LD);
            // permuted output word for column n
            int jn = n / 28, rn = n % 28;
            int wn = 56 * (jn >> 1) + 4 * (rn >> 1) + 2 * (jn & 1) + (rn & 1);
            float* beo = sBe + wn;
            int kb = cb * 4;

            float4 dbuf[12];
            float cs = 0.f;
            #pragma unroll
            for (int t = 0; t < 6; t++) {
                float4 a = wr4[cb + t], b = wt4[cb + t];
                float4 d = make_float4(b.x - a.x, b.y - a.y, b.z - a.z, b.w - a.w);
                dbuf[t] = d;
                cs += (d.x + d.y) + (d.z + d.w);
            }
            #pragma unroll
            for (int j = 0; j < 6; j++) {
                float4 a  = wr4[cb + j + 6], b = wt4[cb + j + 6];
                float4 dn = make_float4(b.x - a.x, b.y - a.y, b.z - a.z, b.w - a.w);
                float4 wo = wr4[cb + j + 3];   // wr_ext[k+12 .. k+15]
                float4 d0 = dbuf[j];
                float S0 = cs + dn.x;
                float S1 = S0 + dn.y - d0.x;
                float S2 = S1 + dn.z - d0.y;
                float S3 = S2 + dn.w - d0.z;
                int k = kb + 4 * j;
                beo[(k + 0) * SB_LD] = wo.x + S0 * (1.0f / 25.0f);
                beo[(k + 1) * SB_LD] = wo.y + S1 * (1.0f / 25.0f);
                beo[(k + 2) * SB_LD] = wo.z + S2 * (1.0f / 25.0f);
                beo[(k + 3) * SB_LD] = wo.w + S3 * (1.0f / 25.0f);
                cs += ((dn.x + dn.y) + (dn.z + dn.w))
                    - ((d0.x + d0.y) + (d0.z + d0.w));
                dbuf[j + 6] = dn;
            }
        }
        __syncthreads();

        // ---- main FMA loop: register double-buffered, f32x2 packed ----
        float4 avb[2];
        ulonglong2 bvb[2][2];   // [buf][g]: g=0 -> pairs j0,j1; g=1 -> j2,j3
        avb[0] = *(const float4*)(pA);
        bvb[0][0] = *(const ulonglong2*)(pB);
        bvb[0][1] = *(const ulonglong2*)(pB + 56 * 4);

        #pragma unroll 8
        for (int k = 0; k < KT; k++) {
            const int cur = k & 1, nxt = cur ^ 1;
            // k=KT-1 prefetch reads one row past the tile: in-bounds smem, discarded
            avb[nxt] = *(const float4*)(pA + (k + 1) * SA_LD);
            const char* pBn = pB + (size_t)(k + 1) * (SB_LD * 4);
            bvb[nxt][0] = *(const ulonglong2*)(pBn);
            bvb[nxt][1] = *(const ulonglong2*)(pBn + 56 * 4);

            unsigned long long a0, a1, a2, a3;
            asm("mov.b64 %0, {%1, %1};" : "=l"(a0) : "f"(avb[cur].x));
            asm("mov.b64 %0, {%1, %1};" : "=l"(a1) : "f"(avb[cur].y));
            asm("mov.b64 %0, {%1, %1};" : "=l"(a2) : "f"(avb[cur].z));
            asm("mov.b64 %0, {%1, %1};" : "=l"(a3) : "f"(avb[cur].w));

            #pragma unroll
            for (int j = 0; j < 4; j++) {
                unsigned long long bb = (j & 1) ? bvb[cur][j >> 1].y
                                                : bvb[cur][j >> 1].x;
                asm("fma.rn.f32x2 %0, %1, %2, %0;" : "+l"(acc[0][j]) : "l"(a0), "l"(bb));
                asm("fma.rn.f32x2 %0, %1, %2, %0;" : "+l"(acc[1][j]) : "l"(a1), "l"(bb));
                asm("fma.rn.f32x2 %0, %1, %2, %0;" : "+l"(acc[2][j]) : "l"(a2), "l"(bb));
                asm("fma.rn.f32x2 %0, %1, %2, %0;" : "+l"(acc[3][j]) : "l"(a3), "l"(bb));
            }
        }
        __syncthreads();   // all readers done with sBe/sA before refill
    }

    // ---- epilogue: add biases, write out[b][c][p] ----
    // acc[i][j] covers p = n0 + 2*tn + 28*j + {0,1}, m = 4*tm + i  (unchanged)
    #pragma unroll
    for (int j = 0; j < 4; j++) {
        int p = n0 + tn * 2 + j * 28;
        float bias0 = bres[(size_t)c * Pp + p]     + btrd[(size_t)c * Pp + p];
        float bias1 = bres[(size_t)c * Pp + p + 1] + btrd[(size_t)c * Pp + p + 1];
        #pragma unroll
        for (int i = 0; i < 4; i++) {
            float lo, hi;
            asm("mov.b64 {%0, %1}, %2;" : "=f"(lo), "=f"(hi) : "l"(acc[i][j]));
            int m = tm * 4 + i;
            float* o = out + ((size_t)m * Cc + c) * Pp + p;
            o[0] = lo + bias0;
            o[1] = hi + bias1;
        }
    }
}

// ---------------------------------------------------------------------------
extern "C" void kernel_launch(void* const* d_in, const int* in_sizes, int n_in,
                              void* d_out, int out_size) {
    (void)in_sizes; (void)n_in; (void)out_size;
    const float* x    = (const float*)d_in[0];
    const float* Wres = (const float*)d_in[1];
    const float* bres = (const float*)d_in[2];
    const float* Wtrd = (const float*)d_in[3];
    const float* btrd = (const float*)d_in[4];
    float* out = (float*)d_out;

    transpose_kernel<<<dim3((Cc + 31) / 32, Sk, Bm / 32), dim3(32, 8)>>>(x);

    cudaFuncSetAttribute(dlinear_gemm,
                         cudaFuncAttributeMaxDynamicSharedMemorySize, SMEM_BYTES);
    dlinear_gemm<<<dim3(Pp / NT, Cc), THREADS, SMEM_BYTES>>>(Wres, bres, Wtrd, btrd, out);
}

// round 14
// speedup vs baseline: 1.5706x; 1.5706x over previous
#include <cuda_runtime.h>
#include <cuda_bf16.h>
#include <cstdint>
#include <cstddef>

// Problem constants
#define Bm   64
#define Sk   720
#define Cc   321
#define Pp   336
#define HALO 12

// Tiling
#define NT     112
#define KT     48
#define NTILES 15
#define NCHUNK 18        // (KT+2*HALO)/4 fp32 chunks per raw-W row
#define THREADS 128      // 4 warps; warp w owns M rows [16w, 16w+16)

// bf16 tile row stride: 56 elems = 112 B (conflict-free ldmatrix, 16B-aligned)
#define BROW 112
// raw W fp32 row stride: 76 words = 304 B (conflict-free strided LDS.128)
#define WROW 304

// smem byte offsets
#define OFF_AH 0                      // A hi: 64 x 112B = 7168
#define OFF_AL 7168                   // A lo
#define OFF_BH 14336                  // B hi: 112 x 112B = 12544
#define OFF_BL 26880                  // B lo
#define OFF_WR 39424                  // raw W_res ext: 112 x 304B = 34048
#define OFF_WT 73472                  // raw W_trd ext
#define SMEM_TOTAL 107520             // -> 2 CTAs/SM

// x split into bf16 hi/lo, layout [c][b][s]
__device__ __nv_bfloat16 g_xhi[(size_t)Cc * Bm * Sk];
__device__ __nv_bfloat16 g_xlo[(size_t)Cc * Bm * Sk];

__device__ __forceinline__ unsigned smem_u32(const void* p) {
    return (unsigned)__cvta_generic_to_shared(p);
}
__device__ __forceinline__ void cp16(unsigned dst, const void* src, unsigned sz) {
    asm volatile("cp.async.ca.shared.global [%0], [%1], 16, %2;"
                 :: "r"(dst), "l"(src), "r"(sz));
}
#define LDSM4(r, addr) \
    asm volatile("ldmatrix.sync.aligned.m8n8.x4.shared.b16 {%0,%1,%2,%3}, [%4];" \
        : "=r"((r)[0]), "=r"((r)[1]), "=r"((r)[2]), "=r"((r)[3]) : "r"(addr))

__device__ __forceinline__ void mma_bf16(float* c, const unsigned* a,
                                         unsigned b0, unsigned b1) {
    asm volatile(
        "mma.sync.aligned.m16n8k16.row.col.f32.bf16.bf16.f32 "
        "{%0,%1,%2,%3}, {%4,%5,%6,%7}, {%8,%9}, {%0,%1,%2,%3};"
        : "+f"(c[0]), "+f"(c[1]), "+f"(c[2]), "+f"(c[3])
        : "r"(a[0]), "r"(a[1]), "r"(a[2]), "r"(a[3]), "r"(b0), "r"(b1));
}

// ---------------------------------------------------------------------------
// Kernel 1: x [b][s][c] fp32 -> g_xhi/g_xlo [c][b][s] bf16 (2-term split)
// ---------------------------------------------------------------------------
__global__ void transpose_split_kernel(const float* __restrict__ x) {
    __shared__ float tile[32][33];
    int b  = blockIdx.z;
    int c0 = blockIdx.x * 32;
    int s0 = blockIdx.y * 32;
    int tx = threadIdx.x, ty = threadIdx.y;

    #pragma unroll
    for (int i = 0; i < 4; i++) {
        int s = s0 + ty + 8*i, c = c0 + tx;
        if (s < Sk && c < Cc)
            tile[ty + 8*i][tx] = x[((size_t)b * Sk + s) * Cc + c];
    }
    __syncthreads();
    #pragma unroll
    for (int i = 0; i < 4; i++) {
        int c = c0 + ty + 8*i, s = s0 + tx;
        if (c < Cc && s < Sk) {
            float v = tile[tx][ty + 8*i];
            __nv_bfloat16 h = __float2bfloat16(v);
            __nv_bfloat16 l = __float2bfloat16(v - __bfloat162float(h));
            size_t o = ((size_t)c * Bm + b) * Sk + s;
            g_xhi[o] = h;
            g_xlo[o] = l;
        }
    }
}

// ---------------------------------------------------------------------------
// Kernel 2: folded GEMM on mma.sync (HMMA bf16, fp32 accum), 2-term split:
//   D = A_hi*B_hi + A_hi*B_lo + A_lo*B_hi
//   W_eff[p,s] = W_res[p,s] + (1/25)*sum_{t in [s-12,s+12] ∩ [0,Sk)} (W_trd-W_res)[p,t]
// A tiles [m][k] bf16 (row-major), B tiles [n][k] bf16 (col-major for mma).
// ---------------------------------------------------------------------------
__global__ __launch_bounds__(THREADS, 2)
void dlinear_hmma(const float* __restrict__ Wres, const float* __restrict__ bres,
                  const float* __restrict__ Wtrd, const float* __restrict__ btrd,
                  float* __restrict__ out)
{
    extern __shared__ char smem[];
    const unsigned sb = smem_u32(smem);
    const int tid  = threadIdx.x;
    const int wid  = tid >> 5;
    const int lane = tid & 31;

    const int c  = blockIdx.y;
    const int n0 = blockIdx.x * NT;

    const float* wr = Wres + ((size_t)c * Pp + n0) * Sk;
    const float* wt = Wtrd + ((size_t)c * Pp + n0) * Sk;
    const __nv_bfloat16* xh = g_xhi + (size_t)c * Bm * Sk;
    const __nv_bfloat16* xl = g_xlo + (size_t)c * Bm * Sk;

    float acc[14][4];
    #pragma unroll
    for (int j = 0; j < 14; j++)
        #pragma unroll
        for (int i = 0; i < 4; i++) acc[j][i] = 0.f;

    // ldmatrix lane address bases
    // A x4: matrices (m0-7,k0-7),(m8-15,k0-7),(m0-7,k8-15),(m8-15,k8-15)
    const unsigned aOff = (unsigned)((16 * wid + (lane & 15)) * BROW + (lane >> 4) * 16);
    // B x4: matrices (n0-7,k0-7),(n0-7,k8-15),(n8-15,k0-7),(n8-15,k8-15)
    const unsigned bOff = (unsigned)((lane & 7) * BROW + ((lane >> 3) & 1) * 16
                                     + ((lane >> 4) & 1) * (8 * BROW));

    for (int it = 0; it < NTILES; it++) {
        const int k0 = it * KT;

        // ---- A tiles via cp.async: 2 parts x 64 rows x 6 chunks = 768 ----
        #pragma unroll
        for (int j = 0; j < 6; j++) {
            int idx  = tid + THREADS * j;
            int part = idx / 384;
            int r    = idx - part * 384;
            int m    = r / 6, ci = r % 6;
            const __nv_bfloat16* src = (part ? xl : xh) + (size_t)m * Sk + k0 + ci * 8;
            unsigned dst = sb + (part ? OFF_AL : OFF_AH) + (unsigned)(m * BROW + ci * 16);
            cp16(dst, src, 16u);
        }
        // ---- raw W ext tiles: 2 arrays x 112 rows x 18 chunks = 4032 ----
        #pragma unroll
        for (int j = 0; j < 32; j++) {
            int idx = tid + THREADS * j;
            if (idx < 2 * NT * NCHUNK) {
                int t   = idx / (NT * NCHUNK);
                int rem = idx - t * (NT * NCHUNK);
                int n   = rem / NCHUNK, ci = rem % NCHUNK;
                int s0  = k0 - HALO + ci * 4;
                unsigned ok = (s0 >= 0 && s0 <= Sk - 4) ? 16u : 0u;
                int s0c = s0 < 0 ? 0 : (s0 > Sk - 4 ? Sk - 4 : s0);
                const float* src = (t ? wt : wr) + (size_t)n * Sk + s0c;
                unsigned dst = sb + (t ? OFF_WT : OFF_WR) + (unsigned)(n * WROW + ci * 16);
                cp16(dst, src, ok);
            }
        }
        asm volatile("cp.async.commit_group;" ::: "memory");
        asm volatile("cp.async.wait_group 0;" ::: "memory");
        __syncthreads();

        // ---- build W_eff row n (fp32 sliding window) -> bf16 hi/lo B tiles ----
        if (tid < NT) {
            const int n = tid;
            const float4* wr4 = (const float4*)(smem + OFF_WR + n * WROW);
            const float4* wt4 = (const float4*)(smem + OFF_WT + n * WROW);
            char* bh = smem + OFF_BH + n * BROW;
            char* bl = smem + OFF_BL + n * BROW;

            float4 dbuf[6];
            float cs = 0.f;
            #pragma unroll
            for (int t = 0; t < 6; t++) {
                float4 a = wr4[t], b = wt4[t];
                float4 d = make_float4(b.x - a.x, b.y - a.y, b.z - a.z, b.w - a.w);
                dbuf[t] = d;
                cs += (d.x + d.y) + (d.z + d.w);
            }
            #pragma unroll
            for (int j = 0; j < 12; j++) {
                float4 a  = wr4[j + 6], b = wt4[j + 6];
                float4 dn = make_float4(b.x - a.x, b.y - a.y, b.z - a.z, b.w - a.w);
                float4 wo = wr4[j + 3];           // wr_ext[4j+12 .. 4j+15]
                float4 d0 = dbuf[j % 6];
                float S0 = cs + dn.x;
                float S1 = S0 + dn.y - d0.x;
                float S2 = S1 + dn.z - d0.y;
                float S3 = S2 + dn.w - d0.z;
                float w0 = wo.x + S0 * (1.0f / 25.0f);
                float w1 = wo.y + S1 * (1.0f / 25.0f);
                float w2 = wo.z + S2 * (1.0f / 25.0f);
                float w3 = wo.w + S3 * (1.0f / 25.0f);

                __nv_bfloat16 h0 = __float2bfloat16(w0), h1 = __float2bfloat16(w1);
                __nv_bfloat16 h2 = __float2bfloat16(w2), h3 = __float2bfloat16(w3);
                __nv_bfloat16 l0 = __float2bfloat16(w0 - __bfloat162float(h0));
                __nv_bfloat16 l1 = __float2bfloat16(w1 - __bfloat162float(h1));
                __nv_bfloat16 l2 = __float2bfloat16(w2 - __bfloat162float(h2));
                __nv_bfloat16 l3 = __float2bfloat16(w3 - __bfloat162float(h3));

                *(unsigned*)(bh + 8 * j) =
                    (unsigned)__bfloat16_as_ushort(h0) | ((unsigned)__bfloat16_as_ushort(h1) << 16);
                *(unsigned*)(bh + 8 * j + 4) =
                    (unsigned)__bfloat16_as_ushort(h2) | ((unsigned)__bfloat16_as_ushort(h3) << 16);
                *(unsigned*)(bl + 8 * j) =
                    (unsigned)__bfloat16_as_ushort(l0) | ((unsigned)__bfloat16_as_ushort(l1) << 16);
                *(unsigned*)(bl + 8 * j + 4) =
                    (unsigned)__bfloat16_as_ushort(l2) | ((unsigned)__bfloat16_as_ushort(l3) << 16);

                cs += ((dn.x + dn.y) + (dn.z + dn.w)) - ((d0.x + d0.y) + (d0.z + d0.w));
                dbuf[j % 6] = dn;
            }
        }
        __syncthreads();

        // ---- HMMA phase: 3 k16-chunks x 7 n-tile-pairs x (2 tiles x 3 products) ----
        #pragma unroll
        for (int kc = 0; kc < 3; kc++) {
            unsigned ah[4], al[4];
            LDSM4(ah, sb + OFF_AH + aOff + kc * 32);
            LDSM4(al, sb + OFF_AL + aOff + kc * 32);
            #pragma unroll
            for (int jp = 0; jp < 7; jp++) {
                unsigned bh[4], bl[4];
                unsigned bbase = bOff + (unsigned)(jp * 16 * BROW) + kc * 32;
                LDSM4(bh, sb + OFF_BH + bbase);
                LDSM4(bl, sb + OFF_BL + bbase);
                mma_bf16(acc[2*jp],     ah, bh[0], bh[1]);
                mma_bf16(acc[2*jp],     ah, bl[0], bl[1]);
                mma_bf16(acc[2*jp],     al, bh[0], bh[1]);
                mma_bf16(acc[2*jp + 1], ah, bh[2], bh[3]);
                mma_bf16(acc[2*jp + 1], ah, bl[2], bl[3]);
                mma_bf16(acc[2*jp + 1], al, bh[2], bh[3]);
            }
        }
        __syncthreads();   // protect sA/sB/sW before next tile's cp.async
    }

    // ---- epilogue ----
    // acc[j]: c0,c1 -> (m = 16*wid + lane/4,      p = n0+8j+2*(lane%4) + {0,1})
    //         c2,c3 -> (m = 16*wid + lane/4 + 8,  same p)
    const int mlo = 16 * wid + (lane >> 2);
    const int pq  = 2 * (lane & 3);
    const float* br = bres + (size_t)c * Pp + n0;
    const float* bt = btrd + (size_t)c * Pp + n0;
    #pragma unroll
    for (int j = 0; j < 14; j++) {
        int p = 8 * j + pq;
        float b0 = br[p] + bt[p];
        float b1 = br[p + 1] + bt[p + 1];
        float2 v0 = make_float2(acc[j][0] + b0, acc[j][1] + b1);
        float2 v1 = make_float2(acc[j][2] + b0, acc[j][3] + b1);
        *(float2*)(out + ((size_t)mlo * Cc + c) * Pp + n0 + p) = v0;
        *(float2*)(out + ((size_t)(mlo + 8) * Cc + c) * Pp + n0 + p) = v1;
    }
}

// ---------------------------------------------------------------------------
extern "C" void kernel_launch(void* const* d_in, const int* in_sizes, int n_in,
                              void* d_out, int out_size) {
    (void)in_sizes; (void)n_in; (void)out_size;
    const float* x    = (const float*)d_in[0];
    const float* Wres = (const float*)d_in[1];
    const float* bres = (const float*)d_in[2];
    const float* Wtrd = (const float*)d_in[3];
    const float* btrd = (const float*)d_in[4];
    float* out = (float*)d_out;

    transpose_split_kernel<<<dim3((Cc + 31) / 32, (Sk + 31) / 32, Bm), dim3(32, 8)>>>(x);

    cudaFuncSetAttribute(dlinear_hmma,
                         cudaFuncAttributeMaxDynamicSharedMemorySize, SMEM_TOTAL);
    dlinear_hmma<<<dim3(Pp / NT, Cc), THREADS, SMEM_TOTAL>>>(Wres, bres, Wtrd, btrd, out);
}

// round 16
// speedup vs baseline: 1.9739x; 1.2568x over previous
#include <cuda_runtime.h>
#include <cuda_bf16.h>
#include <cstdint>
#include <cstddef>

// Problem constants
#define Bm   64
#define Sk   720
#define Cc   321
#define Pp   336
#define HALO 12

// Tiling
#define NT     112
#define KT     48
#define NTILES 15
#define NCHUNK 18        // (KT+2*HALO)/4 fp32 chunks per raw-W row
#define THREADS 256      // 8 warps: mw = wid&3 (16 M rows), ng = wid>>2 (N half)

// bf16 tile row stride: 112 B (conflict-free ldmatrix)
#define BROW 112
// raw W fp32 row stride: 304 B (16B-strided reads conflict-free: 48n mod 128 distinct)
#define WROW 304

// smem layout (bytes)
#define A_SZ   7168                        // 64 x 112B
#define OFF_A(st, part) ((st)*2*A_SZ + (part)*A_SZ)     // 4 bufs: 28672
#define OFF_BH 28672                       // 112 x 112B = 12544
#define OFF_BL 41216
#define W_SZ   34048                       // 112 x 304B
#define OFF_WR(st) (53760 + (st)*W_SZ)
#define OFF_WT(st) (53760 + 2*W_SZ + (st)*W_SZ)
#define SMEM_TOTAL (53760 + 4*W_SZ)        // 189,952 B -> 1 CTA/SM

// x split into bf16 hi/lo, layout [c][b][s]
__device__ __nv_bfloat16 g_xhi[(size_t)Cc * Bm * Sk];
__device__ __nv_bfloat16 g_xlo[(size_t)Cc * Bm * Sk];

__device__ __forceinline__ unsigned smem_u32(const void* p) {
    return (unsigned)__cvta_generic_to_shared(p);
}
__device__ __forceinline__ void cp16(unsigned dst, const void* src, unsigned sz) {
    asm volatile("cp.async.ca.shared.global [%0], [%1], 16, %2;"
                 :: "r"(dst), "l"(src), "r"(sz));
}
#define LDSM4(r, addr) \
    asm volatile("ldmatrix.sync.aligned.m8n8.x4.shared.b16 {%0,%1,%2,%3}, [%4];" \
        : "=r"((r)[0]), "=r"((r)[1]), "=r"((r)[2]), "=r"((r)[3]) : "r"(addr))

__device__ __forceinline__ void mma_bf16(float* c, const unsigned* a,
                                         unsigned b0, unsigned b1) {
    asm volatile(
        "mma.sync.aligned.m16n8k16.row.col.f32.bf16.bf16.f32 "
        "{%0,%1,%2,%3}, {%4,%5,%6,%7}, {%8,%9}, {%0,%1,%2,%3};"
        : "+f"(c[0]), "+f"(c[1]), "+f"(c[2]), "+f"(c[3])
        : "r"(a[0]), "r"(a[1]), "r"(a[2]), "r"(a[3]), "r"(b0), "r"(b1));
}

// ---------------------------------------------------------------------------
// Kernel 1: x [b][s][c] fp32 -> g_xhi/g_xlo [c][b][s] bf16 (2-term split)
// ---------------------------------------------------------------------------
__global__ void transpose_split_kernel(const float* __restrict__ x) {
    __shared__ float tile[32][33];
    int b  = blockIdx.z;
    int c0 = blockIdx.x * 32;
    int s0 = blockIdx.y * 32;
    int tx = threadIdx.x, ty = threadIdx.y;

    #pragma unroll
    for (int i = 0; i < 4; i++) {
        int s = s0 + ty + 8*i, c = c0 + tx;
        if (s < Sk && c < Cc)
            tile[ty + 8*i][tx] = x[((size_t)b * Sk + s) * Cc + c];
    }
    __syncthreads();
    #pragma unroll
    for (int i = 0; i < 4; i++) {
        int c = c0 + ty + 8*i, s = s0 + tx;
        if (c < Cc && s < Sk) {
            float v = tile[tx][ty + 8*i];
            __nv_bfloat16 h = __float2bfloat16(v);
            __nv_bfloat16 l = __float2bfloat16(v - __bfloat162float(h));
            size_t o = ((size_t)c * Bm + b) * Sk + s;
            g_xhi[o] = h;
            g_xlo[o] = l;
        }
    }
}

// ---------------------------------------------------------------------------
// Kernel 2: folded GEMM on mma.sync, 2-deep cp.async pipeline, 8 warps.
//   D = A_hi*B_hi + A_hi*B_lo + A_lo*B_hi
//   W_eff[p,s] = W_res[p,s] + (1/25)*sum_{t in [s-12,s+12] ∩ [0,Sk)} (W_trd-W_res)[p,t]
// Schedule: wait(group i) -> build(i) -> MMA(i) -> issue loads(i+2).
// ---------------------------------------------------------------------------
__global__ __launch_bounds__(THREADS, 1)
void dlinear_hmma(const float* __restrict__ Wres, const float* __restrict__ bres,
                  const float* __restrict__ Wtrd, const float* __restrict__ btrd,
                  float* __restrict__ out)
{
    extern __shared__ char smem[];
    const unsigned sb = smem_u32(smem);
    const int tid  = threadIdx.x;
    const int wid  = tid >> 5;
    const int lane = tid & 31;
    const int mw   = wid & 3;     // 16 M rows each
    const int ng   = wid >> 2;    // 0: jp 0..3, 1: jp 4..6
    const int jp0  = ng ? 4 : 0;
    const int njp  = ng ? 3 : 4;

    const int c  = blockIdx.y;
    const int n0 = blockIdx.x * NT;

    const float* wr = Wres + ((size_t)c * Pp + n0) * Sk;
    const float* wt = Wtrd + ((size_t)c * Pp + n0) * Sk;
    const __nv_bfloat16* xh = g_xhi + (size_t)c * Bm * Sk;
    const __nv_bfloat16* xl = g_xlo + (size_t)c * Bm * Sk;

    float acc[8][4];
    #pragma unroll
    for (int j = 0; j < 8; j++)
        #pragma unroll
        for (int i = 0; i < 4; i++) acc[j][i] = 0.f;

    // ldmatrix lane address bases (same mapping as the verified R14 kernel)
    const unsigned aOff = (unsigned)((16 * mw + (lane & 15)) * BROW + (lane >> 4) * 16);
    const unsigned bOff = (unsigned)((lane & 7) * BROW + ((lane >> 3) & 1) * 16
                                     + ((lane >> 4) & 1) * (8 * BROW));

    // ---- tile-load issuer: one commit group per tile ----
    auto issue_loads = [&](int it) {
        const int st = it & 1;
        const int k0 = it * KT;
        // A: 2 parts x 64 rows x 6 chunks = 768 = 256*3
        #pragma unroll
        for (int j = 0; j < 3; j++) {
            int idx  = tid + THREADS * j;
            int part = idx / 384;
            int r    = idx - part * 384;
            int m    = r / 6, ci = r % 6;
            const __nv_bfloat16* src = (part ? xl : xh) + (size_t)m * Sk + k0 + ci * 8;
            cp16(sb + OFF_A(st, part) + (unsigned)(m * BROW + ci * 16), src, 16u);
        }
        // raw W ext: 2 arrays x 112 rows x 18 chunks = 4032 (< 256*16)
        #pragma unroll
        for (int j = 0; j < 16; j++) {
            int idx = tid + THREADS * j;
            if (idx < 2 * NT * NCHUNK) {
                int t   = idx / (NT * NCHUNK);
                int rem = idx - t * (NT * NCHUNK);
                int n   = rem / NCHUNK, ci = rem % NCHUNK;
                int s0  = k0 - HALO + ci * 4;
                unsigned ok = (s0 >= 0 && s0 <= Sk - 4) ? 16u : 0u;
                int s0c = s0 < 0 ? 0 : (s0 > Sk - 4 ? Sk - 4 : s0);
                const float* src = (t ? wt : wr) + (size_t)n * Sk + s0c;
                cp16(sb + (t ? OFF_WT(st) : OFF_WR(st)) + (unsigned)(n * WROW + ci * 16),
                     src, ok);
            }
        }
        asm volatile("cp.async.commit_group;" ::: "memory");
    };

    issue_loads(0);
    issue_loads(1);

    for (int it = 0; it < NTILES; it++) {
        const int st = it & 1;

        if (it + 1 < NTILES) asm volatile("cp.async.wait_group 1;" ::: "memory");
        else                 asm volatile("cp.async.wait_group 0;" ::: "memory");
        __syncthreads();

        // ---- build W_eff: 224 threads, 2 per row (half-rows of 24 k) ----
        if (tid < 2 * NT) {
            const int n  = tid % NT;
            const int h  = tid / NT;
            const int cb = 6 * h;            // ext chunk base; kb = 24h
            const float4* wr4 = (const float4*)(smem + OFF_WR(st) + n * WROW);
            const float4* wt4 = (const float4*)(smem + OFF_WT(st) + n * WROW);
            char* bh = smem + OFF_BH + n * BROW + 48 * h;
            char* bl = smem + OFF_BL + n * BROW + 48 * h;

            float4 dbuf[6];
            float cs = 0.f;
            #pragma unroll
            for (int t = 0; t < 6; t++) {
                float4 a = wr4[cb + t], b = wt4[cb + t];
                float4 d = make_float4(b.x - a.x, b.y - a.y, b.z - a.z, b.w - a.w);
                dbuf[t] = d;
                cs += (d.x + d.y) + (d.z + d.w);
            }
            #pragma unroll
            for (int j = 0; j < 6; j++) {
                float4 a  = wr4[cb + j + 6], b = wt4[cb + j + 6];
                float4 dn = make_float4(b.x - a.x, b.y - a.y, b.z - a.z, b.w - a.w);
                float4 wo = wr4[cb + j + 3];
                float4 d0 = dbuf[j];
                float S0 = cs + dn.x;
                float S1 = S0 + dn.y - d0.x;
                float S2 = S1 + dn.z - d0.y;
                float S3 = S2 + dn.w - d0.z;
                float w0 = wo.x + S0 * (1.0f / 25.0f);
                float w1 = wo.y + S1 * (1.0f / 25.0f);
                float w2 = wo.z + S2 * (1.0f / 25.0f);
                float w3 = wo.w + S3 * (1.0f / 25.0f);

                __nv_bfloat16 h0 = __float2bfloat16(w0), h1 = __float2bfloat16(w1);
                __nv_bfloat16 h2 = __float2bfloat16(w2), h3 = __float2bfloat16(w3);
                __nv_bfloat16 l0 = __float2bfloat16(w0 - __bfloat162float(h0));
                __nv_bfloat16 l1 = __float2bfloat16(w1 - __bfloat162float(h1));
                __nv_bfloat16 l2 = __float2bfloat16(w2 - __bfloat162float(h2));
                __nv_bfloat16 l3 = __float2bfloat16(w3 - __bfloat162float(h3));

                *(unsigned*)(bh + 8 * j) =
                    (unsigned)__bfloat16_as_ushort(h0) | ((unsigned)__bfloat16_as_ushort(h1) << 16);
                *(unsigned*)(bh + 8 * j + 4) =
                    (unsigned)__bfloat16_as_ushort(h2) | ((unsigned)__bfloat16_as_ushort(h3) << 16);
                *(unsigned*)(bl + 8 * j) =
                    (unsigned)__bfloat16_as_ushort(l0) | ((unsigned)__bfloat16_as_ushort(l1) << 16);
                *(unsigned*)(bl + 8 * j + 4) =
                    (unsigned)__bfloat16_as_ushort(l2) | ((unsigned)__bfloat16_as_ushort(l3) << 16);

                cs += ((dn.x + dn.y) + (dn.z + dn.w)) - ((d0.x + d0.y) + (d0.z + d0.w));
                dbuf[j] = dn;
            }
        }
        __syncthreads();

        // ---- HMMA phase ----
        #pragma unroll
        for (int kc = 0; kc < 3; kc++) {
            unsigned ah[4], al[4];
            LDSM4(ah, sb + OFF_A(st, 0) + aOff + kc * 32);
            LDSM4(al, sb + OFF_A(st, 1) + aOff + kc * 32);
            #pragma unroll
            for (int jpl = 0; jpl < 4; jpl++) {
                if (jpl < njp) {
                    int jp = jp0 + jpl;
                    unsigned bhf[4], blf[4];
                    unsigned bbase = bOff + (unsigned)(jp * 16 * BROW) + kc * 32;
                    LDSM4(bhf, sb + OFF_BH + bbase);
                    LDSM4(blf, sb + OFF_BL + bbase);
                    mma_bf16(acc[2*jpl],     ah, bhf[0], bhf[1]);
                    mma_bf16(acc[2*jpl],     ah, blf[0], blf[1]);
                    mma_bf16(acc[2*jpl],     al, bhf[0], bhf[1]);
                    mma_bf16(acc[2*jpl + 1], ah, bhf[2], bhf[3]);
                    mma_bf16(acc[2*jpl + 1], ah, blf[2], blf[3]);
                    mma_bf16(acc[2*jpl + 1], al, bhf[2], bhf[3]);
                }
            }
        }
        __syncthreads();   // buffers free before reissue

        if (it + 2 < NTILES) issue_loads(it + 2);
    }

    // ---- epilogue: add biases, write out[b][c][p] ----
    const int mlo = 16 * mw + (lane >> 2);
    const int pq  = 2 * (lane & 3);
    const float* br = bres + (size_t)c * Pp + n0;
    const float* bt = btrd + (size_t)c * Pp + n0;
    #pragma unroll
    for (int jpl = 0; jpl < 4; jpl++) {
        if (jpl < njp) {
            #pragma unroll
            for (int t = 0; t < 2; t++) {
                int jg = 2 * (jp0 + jpl) + t;       // global n8 tile 0..13
                int p  = 8 * jg + pq;
                float b0 = br[p] + bt[p];
                float b1 = br[p + 1] + bt[p + 1];
                float* a = acc[2 * jpl + t];
                *(float2*)(out + ((size_t)mlo * Cc + c) * Pp + n0 + p) =
                    make_float2(a[0] + b0, a[1] + b1);
                *(float2*)(out + ((size_t)(mlo + 8) * Cc + c) * Pp + n0 + p) =
                    make_float2(a[2] + b0, a[3] + b1);
            }
        }
    }
}

// ---------------------------------------------------------------------------
extern "C" void kernel_launch(void* const* d_in, const int* in_sizes, int n_in,
                              void* d_out, int out_size) {
    (void)in_sizes; (void)n_in; (void)out_size;
    const float* x    = (const float*)d_in[0];
    const float* Wres = (const float*)d_in[1];
    const float* bres = (const float*)d_in[2];
    const float* Wtrd = (const float*)d_in[3];
    const float* btrd = (const float*)d_in[4];
    float* out = (float*)d_out;

    transpose_split_kernel<<<dim3((Cc + 31) / 32, (Sk + 31) / 32, Bm), dim3(32, 8)>>>(x);

    cudaFuncSetAttribute(dlinear_hmma,
                         cudaFuncAttributeMaxDynamicSharedMemorySize, SMEM_TOTAL);
    dlinear_hmma<<<dim3(Pp / NT, Cc), THREADS, SMEM_TOTAL>>>(Wres, bres, Wtrd, btrd, out);
}